// round 15
// baseline (speedup 1.0000x reference)
#include <cuda_runtime.h>
#include <cuda_fp16.h>
#include <cstdint>

#define T_ 65536
#define D_ 256
#define CHUNK 128
#define NCH (T_/CHUNK)   // 512

// ================= device scratch (no allocations allowed) =================
__device__ float g_af [T_*D_];
__device__ float g_bf [T_*D_];
__device__ float g_ab2[T_*D_];
__device__ float g_bb2[T_*D_];
__device__ float g_cA [2*NCH*D_];
__device__ float g_cB [2*NCH*D_];
__device__ float g_pref[2*NCH*D_];
__device__ float g_hbias[2][D_];        // layer0: bh + q0 @ Wh_bottom

__device__ __half g_xhi[T_*D_];                    // x hi (H-phase A operand)
__device__ __half g_uhi[T_*D_], g_ulo[T_*D_];      // u = x*q hi/lo (Z-phase)
__device__ __half g_qhi[T_*D_];                    // q hi (H-phase A operand)
__device__ __half g_wzT[5][D_*D_];      // [layerdir][n*256+k]
__device__ __half g_whT[5][D_*2*D_];    // [layerdir][n*512+k]

// ================= helpers =================
__device__ __forceinline__ uint32_t smem_u32(const void* p) {
    uint32_t a;
    asm("{ .reg .u64 t; cvta.to.shared.u64 t, %1; cvt.u32.u64 %0, t; }" : "=r"(a) : "l"(p));
    return a;
}
__device__ __forceinline__ void ldsm_x4(uint32_t (&r)[4], uint32_t addr) {
    asm volatile("ldmatrix.sync.aligned.m8n8.x4.shared.b16 {%0,%1,%2,%3}, [%4];"
                 : "=r"(r[0]), "=r"(r[1]), "=r"(r[2]), "=r"(r[3]) : "r"(addr));
}
__device__ __forceinline__ void mma16816(float (&d)[4], const uint32_t (&a)[4], const uint32_t* b) {
    asm volatile("mma.sync.aligned.m16n8k16.row.col.f32.f16.f16.f32 "
                 "{%0,%1,%2,%3}, {%4,%5,%6,%7}, {%8,%9}, {%0,%1,%2,%3};"
                 : "+f"(d[0]), "+f"(d[1]), "+f"(d[2]), "+f"(d[3])
                 : "r"(a[0]), "r"(a[1]), "r"(a[2]), "r"(a[3]), "r"(b[0]), "r"(b[1]));
}
__device__ __forceinline__ void cpa16(uint32_t dst, const void* src) {
    asm volatile("cp.async.cg.shared.global [%0], [%1], 16;" :: "r"(dst), "l"(src));
}
#define CP_COMMIT() asm volatile("cp.async.commit_group;" ::: "memory")
#define CP_WAIT1()  asm volatile("cp.async.wait_group 1;" ::: "memory")

__device__ __forceinline__ float sigf(float v)   { return 1.0f/(1.0f+__expf(-v)); }
__device__ __forceinline__ float tanhf_(float v) { return 1.0f - 2.0f/(__expf(2.0f*v)+1.0f); }
__device__ __forceinline__ void split2h(float v, __half& h, __half& l) {
    h = __float2half_rn(v);
    l = __float2half_rn(v - __half2float(h));
}

// ================= prep kernels =================
// ALL weight transposes in one launch: blockIdx.z encodes (ld, mz): z = ld*2 + mz
__global__ void prep_w(const float* __restrict__ Wz0, const float* __restrict__ Wh0,
                       const float* __restrict__ Wz1, const float* __restrict__ Wh1,
                       const float* __restrict__ Wz2, const float* __restrict__ Wh2,
                       const float* __restrict__ Wz3, const float* __restrict__ Wh3,
                       const float* __restrict__ Wz4, const float* __restrict__ Wh4)
{
    int ld = blockIdx.z >> 1, mz = blockIdx.z & 1;
    if (mz == 0 && blockIdx.y >= 8) return;
    const float* srcs[10] = {Wz0, Wh0, Wz1, Wh1, Wz2, Wh2, Wz3, Wh3, Wz4, Wh4};
    const float* src = srcs[blockIdx.z];
    int Krows = mz ? 512 : 256;
    __half* dh = mz ? &g_whT[ld][0] : &g_wzT[ld][0];
    int k0 = blockIdx.y*32, n0 = blockIdx.x*32;
    int tx = threadIdx.x, ty = threadIdx.y;
    __shared__ float t[32][33];
    #pragma unroll
    for (int i = 0; i < 4; i++)
        t[ty + i*8][tx] = src[(size_t)(k0 + ty + i*8)*256 + n0 + tx];
    __syncthreads();
    #pragma unroll
    for (int i = 0; i < 4; i++)
        dh[(size_t)(n0 + ty + i*8)*Krows + k0 + tx] = __float2half_rn(t[tx][ty + i*8]);
}

// x hi + u0 = x*q hi/lo (single story read)
__global__ void prep_xu(const float* __restrict__ story, const float* __restrict__ q)
{
    size_t i = ((size_t)blockIdx.x*256 + threadIdx.x)*2;
    int d = (int)(i & (D_-1));
    float2 v = *(const float2*)(story + i);
    __half2 ph;
    ph.x = __float2half_rn(v.x); ph.y = __float2half_rn(v.y);
    *(__half2*)(g_xhi+i) = ph;
    float u0 = v.x * q[d], u1 = v.y * q[d+1];
    __half h0,l0,h1,l1;
    split2h(u0,h0,l0); split2h(u1,h1,l1);
    __half2 pu, pl; pu.x=h0; pu.y=h1; pl.x=l0; pl.y=l1;
    *(__half2*)(g_uhi+i) = pu; *(__half2*)(g_ulo+i) = pl;
}

// warp-per-(dir,n): hbias[dir][n] = bh[n] + sum_k q[k]*Wh[(256+k)*256+n]
__global__ void qwh0(const float* __restrict__ Whf, const float* __restrict__ bhf,
                     const float* __restrict__ Whb, const float* __restrict__ bhb,
                     const float* __restrict__ q)
{
    int gw = (blockIdx.x * blockDim.x + threadIdx.x) >> 5;
    int lane = threadIdx.x & 31;
    int dir = gw >> 8, n = gw & 255;
    const float* Wh = dir ? Whb : Whf;
    const float* bh = dir ? bhb : bhf;
    float acc = 0.f;
    #pragma unroll
    for (int kk = 0; kk < 8; kk++) {
        int k = kk*32 + lane;
        acc = fmaf(q[k], Wh[(size_t)(256+k)*256 + n], acc);
    }
    #pragma unroll
    for (int o = 16; o; o >>= 1) acc += __shfl_xor_sync(0xFFFFFFFFu, acc, o);
    if (lane == 0) g_hbias[dir][n] = bh[n] + acc;
}

// ================= fused GEMM (mma.sync fp16, M=128 x N=32 tiles, 4 CTAs/SM) =================
// Z = [uhi; ulo] @ [Wz; Wz] (K-concat).
// Stage 12800B: A 128x32h (10240, 80B row pad) | B 32x32h (2560).
// 2-stage double buffer; strength-reduced issue; hoisted LDSM addrs.
// SMEM: [0,25600) stages | [25600,44032) zbuf fp32 128x36. bbuf (18432) aliases stages.
#define STAGE_B 12800
#define ZBUF_OFF 25600
#define SM_TOTAL 44032

__global__ __launch_bounds__(256, 4)
void qrn_gemm(int ld_f, int ld_b, int layer0, int store_ab,
              const float* __restrict__ bz_f_, const float* __restrict__ bz_b_,
              const float* __restrict__ bh_f_, const float* __restrict__ bh_b_)
{
    extern __shared__ __align__(16) char smem[];
    float* bbuf = (float*)smem;                      // aliases stages post-mainloop (18432 <= 25600)
    float* zbuf = (float*)(smem + ZBUF_OFF);         // 128 x 36 fp32
    __shared__ float s_bz[32], s_bh[32];
    __shared__ float s_pA[8][32], s_pB[8][32];

    const int tid = threadIdx.x, lane = tid & 31, warp = tid >> 5;
    const int wm = warp & 3, wn = warp >> 2;         // 4M x 2N warps; warp tile 32x16
    const int ch = blockIdx.y;
    const int dir = blockIdx.z;
    const int ld = dir ? ld_b : ld_f;
    const int row0 = ch*CHUNK, n0g = blockIdx.x*32;
    const uint32_t base = smem_u32(smem);

    if (tid < 32) {
        s_bz[tid] = (dir ? bz_b_ : bz_f_)[n0g + tid];
        s_bh[tid] = layer0 ? g_hbias[dir][n0g + tid]
                           : (dir ? bh_b_ : bh_f_)[n0g + tid];
    }

    const __half* wz = &g_wzT[ld][0];
    const __half* wh = &g_whT[ld][0];
    const int S = layer0 ? 24 : 32;     // phases of 8: uhi@Wz, ulo@Wz, x@WhTop, q@WhBot

    // ---- thread-constant copy geometry ----
    const int rA = tid >> 2, qq = tid & 3;
    const uint32_t dstA0 = (uint32_t)(rA*80 + qq*16);    // A rows 0..63
    const uint32_t dstA1 = dstA0 + 5120;                 // A rows 64..127
    const uint32_t dstB  = 10240 + dstA0;                // B rows 0..31 (tid<128 only)

    // ---- hoisted LDSM lane offsets (bytes, within stage) ----
    uint32_t roff[2];
    #pragma unroll
    for (int mi = 0; mi < 2; mi++)
        roff[mi] = (uint32_t)(wm*32 + mi*16 + (lane & 15))*80
                 + (uint32_t)(((lane >> 4) << 3)*2);
    const uint32_t boff = 10240
                 + (uint32_t)(wn*16 + ((lane >> 4) << 3) + (lane & 7))*80
                 + (uint32_t)((((lane >> 3) & 1) << 3)*2);

    // ---- running source pointers (reset per 8-step phase) ----
    const __half *pA0, *pB;
    auto set_ptrs = [&](int s) {
        int ph = s >> 3, k = (s & 7)*32;
        const __half* Ab = (ph == 0) ? g_uhi : (ph == 1) ? g_ulo
                          : (ph == 2) ? g_xhi : g_qhi;
        pA0 = Ab + (size_t)(row0 + rA)*256 + k + qq*8;
        if (ph < 2) pB = wz + (size_t)(n0g + rA)*256 + k + qq*8;
        else        pB = wh + (size_t)(n0g + rA)*512 + ((ph == 3) ? 256 : 0) + k + qq*8;
    };

    float acc[2][2][4];
    #pragma unroll
    for (int mi = 0; mi < 2; mi++)
        #pragma unroll
        for (int ni = 0; ni < 2; ni++)
            #pragma unroll
            for (int j = 0; j < 4; j++) acc[mi][ni][j] = 0.f;

    // prologue: issue stage 0; point at stage 1
    set_ptrs(0);
    cpa16(base + dstA0, pA0); cpa16(base + dstA1, pA0 + 16384);
    if (tid < 128) cpa16(base + dstB, pB);
    CP_COMMIT();
    set_ptrs(1);

    for (int s = 0; s < S; s++) {
        __syncthreads();   // all warps done reading buffer (s+1)&1 (from iter s-1)
        if (s + 1 < S) {
            uint32_t sb = base + (uint32_t)(((s+1) & 1)*STAGE_B);
            cpa16(sb + dstA0, pA0); cpa16(sb + dstA1, pA0 + 16384);
            if (tid < 128) cpa16(sb + dstB, pB);
            if (s + 2 < S) {
                if (((s + 2) & 7) == 0) set_ptrs(s + 2);
                else { pA0 += 32; pB += 32; }
            }
        }
        CP_COMMIT();
        CP_WAIT1();        // stage s arrived
        __syncthreads();

        {   // ---- mma step on stage s ----
            const uint32_t stg = base + (uint32_t)((s & 1)*STAGE_B);
            #pragma unroll
            for (int kk = 0; kk < 2; kk++) {
                const uint32_t kof = kk*32;     // 16 halves
                uint32_t aH[2][4], bb[2][2], t[4];
                ldsm_x4(aH[0], stg + roff[0] + kof);
                ldsm_x4(aH[1], stg + roff[1] + kof);
                ldsm_x4(t, stg + boff + kof);
                bb[0][0]=t[0]; bb[0][1]=t[1]; bb[1][0]=t[2]; bb[1][1]=t[3];
                #pragma unroll
                for (int mi = 0; mi < 2; mi++)
                    #pragma unroll
                    for (int ni = 0; ni < 2; ni++)
                        mma16816(acc[mi][ni], aH[mi], bb[ni]);
            }
        }

        if (s == 15) {     // z epilogue -> zbuf, reset acc for H phase
            #pragma unroll
            for (int mi = 0; mi < 2; mi++) {
                int r0 = wm*32 + mi*16 + (lane >> 2);
                #pragma unroll
                for (int ni = 0; ni < 2; ni++) {
                    int cl = wn*16 + ni*8 + (lane & 3)*2;
                    zbuf[r0*36 + cl]     = sigf(acc[mi][ni][0] + s_bz[cl]);
                    zbuf[r0*36 + cl + 1] = sigf(acc[mi][ni][1] + s_bz[cl+1]);
                    zbuf[(r0+8)*36 + cl]     = sigf(acc[mi][ni][2] + s_bz[cl]);
                    zbuf[(r0+8)*36 + cl + 1] = sigf(acc[mi][ni][3] + s_bz[cl+1]);
                    #pragma unroll
                    for (int j = 0; j < 4; j++) acc[mi][ni][j] = 0.f;
                }
            }
        }
    }
    __syncthreads();   // all MMA done; stage smem reusable as bbuf

    // ---- final epilogue: a = 1-z (into zbuf), b = z*tanh(h+bh) -> bbuf ----
    #pragma unroll
    for (int mi = 0; mi < 2; mi++) {
        int r0 = wm*32 + mi*16 + (lane >> 2);
        #pragma unroll
        for (int ni = 0; ni < 2; ni++) {
            int cl = wn*16 + ni*8 + (lane & 3)*2;
            #pragma unroll
            for (int hrow = 0; hrow < 2; hrow++) {
                int r = r0 + hrow*8;
                float z0 = zbuf[r*36 + cl], z1 = zbuf[r*36 + cl + 1];
                float h0 = tanhf_(acc[mi][ni][hrow*2+0] + s_bh[cl]);
                float h1 = tanhf_(acc[mi][ni][hrow*2+1] + s_bh[cl+1]);
                bbuf[r*36 + cl]     = z0*h0;
                bbuf[r*36 + cl + 1] = z1*h1;
                zbuf[r*36 + cl]     = 1.0f - z0;
                zbuf[r*36 + cl + 1] = 1.0f - z1;
            }
        }
    }
    __syncthreads();

    // ---- global a,b stores (128 rows x 32 cols) ----
    if (store_ab) {
        float* outA = dir ? g_ab2 : g_af;
        float* outB = dir ? g_bb2 : g_bf;
        #pragma unroll
        for (int i = 0; i < 4; i++) {
            int v = tid + i*256;          // 0..1023
            int r = v >> 3, c4 = (v & 7)*4;
            float4 va = *(float4*)(zbuf + r*36 + c4);
            float4 vb = *(float4*)(bbuf + r*36 + c4);
            size_t o = (size_t)(row0 + r)*256 + n0g + c4;
            *(float4*)(outA + o) = va;
            *(float4*)(outB + o) = vb;
        }
    }

    // ---- per-chunk scan composites (8 segs x 16 rows) ----
    {
        int cc = tid & 31, seg = tid >> 5;
        float pa = 1.0f, pb = 0.0f;
        if (dir == 0) {
            #pragma unroll 4
            for (int r = seg*16; r < seg*16 + 16; r++) {
                float a = zbuf[r*36 + cc], b = bbuf[r*36 + cc];
                pb = fmaf(a, pb, b); pa *= a;
            }
        } else {
            #pragma unroll 4
            for (int r = seg*16 + 15; r >= seg*16; r--) {
                float a = zbuf[r*36 + cc], b = bbuf[r*36 + cc];
                pb = fmaf(a, pb, b); pa *= a;
            }
        }
        s_pA[seg][cc] = pa; s_pB[seg][cc] = pb;
    }
    __syncthreads();
    if (tid < 32) {
        float A = 1.0f, B = 0.0f;
        if (dir == 0) {
            #pragma unroll
            for (int s = 0; s < 8; s++) { B = fmaf(s_pA[s][tid], B, s_pB[s][tid]); A *= s_pA[s][tid]; }
        } else {
            #pragma unroll
            for (int s = 7; s >= 0; s--) { B = fmaf(s_pA[s][tid], B, s_pB[s][tid]); A *= s_pA[s][tid]; }
        }
        size_t o = ((size_t)dir*NCH + ch)*256 + n0g + tid;
        g_cA[o] = A; g_cB[o] = B;
    }
}

// ================= scan kernels =================
__global__ __launch_bounds__(256) void scan_prefix()
{
    int dir = blockIdx.x, d = threadIdx.x;
    float cB = 0.f;
    if (dir == 0) {
        for (int c0 = 0; c0 < NCH; c0 += 8) {
            float a[8], b[8];
            #pragma unroll
            for (int i = 0; i < 8; i++) {
                a[i] = g_cA[(c0+i)*D_ + d];
                b[i] = g_cB[(c0+i)*D_ + d];
            }
            #pragma unroll
            for (int i = 0; i < 8; i++) {
                g_pref[(c0+i)*D_ + d] = cB;
                cB = fmaf(a[i], cB, b[i]);
            }
        }
    } else {
        for (int c0 = NCH - 8; c0 >= 0; c0 -= 8) {
            float a[8], b[8];
            #pragma unroll
            for (int i = 0; i < 8; i++) {
                a[i] = g_cA[(NCH + c0+i)*D_ + d];
                b[i] = g_cB[(NCH + c0+i)*D_ + d];
            }
            #pragma unroll
            for (int i = 7; i >= 0; i--) {
                g_pref[(NCH + c0+i)*D_ + d] = cB;
                cB = fmaf(a[i], cB, b[i]);
            }
        }
    }
}

// fused fwd+bwd apply + next-layer operand prep (h_fwd staged in smem)
__global__ __launch_bounds__(256) void scan_apply(const float* __restrict__ story)
{
    extern __shared__ float hbuf[];   // 128 x 256
    int d = threadIdx.x, ch = blockIdx.x;

    float h = g_pref[ch*D_ + d];
    size_t base = (size_t)ch*CHUNK*D_ + d;
    for (int j0 = 0; j0 < CHUNK; j0 += 8) {
        float a[8], b[8];
        #pragma unroll
        for (int i = 0; i < 8; i++) {
            size_t o = base + (size_t)(j0+i)*D_;
            a[i] = g_af[o]; b[i] = g_bf[o];
        }
        #pragma unroll
        for (int i = 0; i < 8; i++) {
            h = fmaf(a[i], h, b[i]);
            hbuf[(j0+i)*256 + d] = h;
        }
    }
    __syncthreads();

    float h2 = g_pref[(NCH + ch)*D_ + d];
    size_t base2 = ((size_t)ch*CHUNK + CHUNK-1)*D_ + d;
    for (int j0 = 0; j0 < CHUNK; j0 += 8) {
        float a[8], b[8], x[8];
        #pragma unroll
        for (int i = 0; i < 8; i++) {
            size_t o = base2 - (size_t)(j0+i)*D_;
            a[i] = g_ab2[o]; b[i] = g_bb2[o]; x[i] = story[o];
        }
        #pragma unroll
        for (int i = 0; i < 8; i++) {
            size_t o = base2 - (size_t)(j0+i)*D_;
            h2 = fmaf(a[i], h2, b[i]);
            float q = hbuf[(CHUNK-1-(j0+i))*256 + d] + h2;
            float u = x[i] * q;
            __half uh, ul;
            split2h(u, uh, ul);
            g_qhi[o] = __float2half_rn(q);
            g_uhi[o] = uh; g_ulo[o] = ul;
        }
    }
}

__global__ __launch_bounds__(256) void scan_final(float* __restrict__ out)
{
    int d = threadIdx.x;
    float cB = 0.f;
    for (int c0 = 0; c0 < NCH; c0 += 8) {
        float a[8], b[8];
        #pragma unroll
        for (int i = 0; i < 8; i++) {
            a[i] = g_cA[(c0+i)*D_ + d];
            b[i] = g_cB[(c0+i)*D_ + d];
        }
        #pragma unroll
        for (int i = 0; i < 8; i++)
            cB = fmaf(a[i], cB, b[i]);
    }
    out[d] = cB;
}

// ================= host launcher =================
extern "C" void kernel_launch(void* const* d_in, const int* in_sizes, int n_in,
                              void* d_out, int out_size)
{
    const float* story    = (const float*)d_in[0];
    const float* question = (const float*)d_in[1];
    const float* Wz_f     = (const float*)d_in[2];
    const float* bz_f     = (const float*)d_in[3];
    const float* Wh_f     = (const float*)d_in[4];
    const float* bh_f     = (const float*)d_in[5];
    const float* Wz_b     = (const float*)d_in[6];
    const float* bz_b     = (const float*)d_in[7];
    const float* Wh_b     = (const float*)d_in[8];
    const float* bh_b     = (const float*)d_in[9];
    float* out = (float*)d_out;

    cudaFuncSetAttribute(qrn_gemm,   cudaFuncAttributeMaxDynamicSharedMemorySize, SM_TOTAL);
    cudaFuncSetAttribute(scan_apply, cudaFuncAttributeMaxDynamicSharedMemorySize, 131072);

    // launch order: 3 predecessors then gemm at my-index 3 (ncu fixed window lands there)
    dim3 wb(32, 8), wg(8, 16, 10);
    prep_w<<<wg, wb>>>(Wz_f,           Wh_f,
                       Wz_b,           Wh_b,
                       Wz_f + 65536,   Wh_f + 131072,
                       Wz_b + 65536,   Wh_b + 131072,
                       Wz_f + 2*65536, Wh_f + 2*131072);
    prep_xu<<<T_*D_/512, 256>>>(story, question);
    qwh0<<<128, 128>>>(Wh_f, bh_f, Wh_b, bh_b, question);

    dim3 gg2(8, NCH, 2);   // (N-eighth, chunk, dir)
    dim3 gg1(8, NCH, 1);

    // ---- layer 0 (fwd+bwd merged) ----  <- my launch index 3: ncu capture target
    qrn_gemm<<<gg2, 256, SM_TOTAL>>>(0, 1, 1, 1, bz_f, bz_b, nullptr, nullptr);
    scan_prefix<<<2, 256>>>();
    scan_apply<<<NCH, 256, 131072>>>(story);

    // ---- layer 1 ----
    qrn_gemm<<<gg2, 256, SM_TOTAL>>>(2, 3, 0, 1, bz_f + 256, bz_b + 256, bh_f + 256, bh_b + 256);
    scan_prefix<<<2, 256>>>();
    scan_apply<<<NCH, 256, 131072>>>(story);

    // ---- layer 2 (forward only; composites only) ----
    qrn_gemm<<<gg1, 256, SM_TOTAL>>>(4, 4, 0, 0, bz_f + 512, bz_b + 512, bh_f + 512, bh_b + 512);
    scan_final<<<1, 256>>>(out);
}

// round 17
// speedup vs baseline: 1.4365x; 1.4365x over previous
#include <cuda_runtime.h>
#include <cuda_fp16.h>
#include <cstdint>

#define T_ 65536
#define D_ 256
#define CHUNK 128
#define NCH (T_/CHUNK)   // 512

// ================= device scratch (no allocations allowed) =================
__device__ float g_af [T_*D_];
__device__ float g_bf [T_*D_];
__device__ float g_ab2[T_*D_];
__device__ float g_bb2[T_*D_];
__device__ float g_cA [2*NCH*D_];
__device__ float g_cB [2*NCH*D_];
__device__ float g_pref[2*NCH*D_];
__device__ float g_hbias[2][D_];        // layer0: bh + q0 @ Wh_bottom

__device__ __half g_xhi[T_*D_];                    // x hi (H-phase A operand)
__device__ __half g_uhi[T_*D_], g_ulo[T_*D_];      // u = x*q hi/lo (Z-phase)
__device__ __half g_qhi[T_*D_];                    // q hi (H-phase A operand)
__device__ __half g_wzT[5][D_*D_];      // [layerdir][n*256+k]
__device__ __half g_whT[5][D_*2*D_];    // [layerdir][n*512+k]

// ================= helpers =================
__device__ __forceinline__ uint32_t smem_u32(const void* p) {
    uint32_t a;
    asm("{ .reg .u64 t; cvta.to.shared.u64 t, %1; cvt.u32.u64 %0, t; }" : "=r"(a) : "l"(p));
    return a;
}
__device__ __forceinline__ void ldsm_x4(uint32_t (&r)[4], uint32_t addr) {
    asm volatile("ldmatrix.sync.aligned.m8n8.x4.shared.b16 {%0,%1,%2,%3}, [%4];"
                 : "=r"(r[0]), "=r"(r[1]), "=r"(r[2]), "=r"(r[3]) : "r"(addr));
}
__device__ __forceinline__ void mma16816(float (&d)[4], const uint32_t (&a)[4], const uint32_t* b) {
    asm volatile("mma.sync.aligned.m16n8k16.row.col.f32.f16.f16.f32 "
                 "{%0,%1,%2,%3}, {%4,%5,%6,%7}, {%8,%9}, {%0,%1,%2,%3};"
                 : "+f"(d[0]), "+f"(d[1]), "+f"(d[2]), "+f"(d[3])
                 : "r"(a[0]), "r"(a[1]), "r"(a[2]), "r"(a[3]), "r"(b[0]), "r"(b[1]));
}
__device__ __forceinline__ void cpa16(uint32_t dst, const void* src) {
    asm volatile("cp.async.cg.shared.global [%0], [%1], 16;" :: "r"(dst), "l"(src));
}
#define CP_COMMIT() asm volatile("cp.async.commit_group;" ::: "memory")
#define CP_WAIT1()  asm volatile("cp.async.wait_group 1;" ::: "memory")

__device__ __forceinline__ float sigf(float v)   { return 1.0f/(1.0f+__expf(-v)); }
__device__ __forceinline__ float tanhf_(float v) { return 1.0f - 2.0f/(__expf(2.0f*v)+1.0f); }
__device__ __forceinline__ void split2h(float v, __half& h, __half& l) {
    h = __float2half_rn(v);
    l = __float2half_rn(v - __half2float(h));
}

// ================= prep kernels =================
// ALL weight transposes in one launch: blockIdx.z encodes (ld, mz): z = ld*2 + mz
__global__ void prep_w(const float* __restrict__ Wz0, const float* __restrict__ Wh0,
                       const float* __restrict__ Wz1, const float* __restrict__ Wh1,
                       const float* __restrict__ Wz2, const float* __restrict__ Wh2,
                       const float* __restrict__ Wz3, const float* __restrict__ Wh3,
                       const float* __restrict__ Wz4, const float* __restrict__ Wh4)
{
    int ld = blockIdx.z >> 1, mz = blockIdx.z & 1;
    if (mz == 0 && blockIdx.y >= 8) return;
    const float* srcs[10] = {Wz0, Wh0, Wz1, Wh1, Wz2, Wh2, Wz3, Wh3, Wz4, Wh4};
    const float* src = srcs[blockIdx.z];
    int Krows = mz ? 512 : 256;
    __half* dh = mz ? &g_whT[ld][0] : &g_wzT[ld][0];
    int k0 = blockIdx.y*32, n0 = blockIdx.x*32;
    int tx = threadIdx.x, ty = threadIdx.y;
    __shared__ float t[32][33];
    #pragma unroll
    for (int i = 0; i < 4; i++)
        t[ty + i*8][tx] = src[(size_t)(k0 + ty + i*8)*256 + n0 + tx];
    __syncthreads();
    #pragma unroll
    for (int i = 0; i < 4; i++)
        dh[(size_t)(n0 + ty + i*8)*Krows + k0 + tx] = __float2half_rn(t[tx][ty + i*8]);
}

// x hi + u0 = x*q hi/lo (single story read)
__global__ void prep_xu(const float* __restrict__ story, const float* __restrict__ q)
{
    size_t i = ((size_t)blockIdx.x*256 + threadIdx.x)*2;
    int d = (int)(i & (D_-1));
    float2 v = *(const float2*)(story + i);
    __half2 ph;
    ph.x = __float2half_rn(v.x); ph.y = __float2half_rn(v.y);
    *(__half2*)(g_xhi+i) = ph;
    float u0 = v.x * q[d], u1 = v.y * q[d+1];
    __half h0,l0,h1,l1;
    split2h(u0,h0,l0); split2h(u1,h1,l1);
    __half2 pu, pl; pu.x=h0; pu.y=h1; pl.x=l0; pl.y=l1;
    *(__half2*)(g_uhi+i) = pu; *(__half2*)(g_ulo+i) = pl;
}

// warp-per-(dir,n): hbias[dir][n] = bh[n] + sum_k q[k]*Wh[(256+k)*256+n]
__global__ void qwh0(const float* __restrict__ Whf, const float* __restrict__ bhf,
                     const float* __restrict__ Whb, const float* __restrict__ bhb,
                     const float* __restrict__ q)
{
    int gw = (blockIdx.x * blockDim.x + threadIdx.x) >> 5;
    int lane = threadIdx.x & 31;
    int dir = gw >> 8, n = gw & 255;
    const float* Wh = dir ? Whb : Whf;
    const float* bh = dir ? bhb : bhf;
    float acc = 0.f;
    #pragma unroll
    for (int kk = 0; kk < 8; kk++) {
        int k = kk*32 + lane;
        acc = fmaf(q[k], Wh[(size_t)(256+k)*256 + n], acc);
    }
    #pragma unroll
    for (int o = 16; o; o >>= 1) acc += __shfl_xor_sync(0xFFFFFFFFu, acc, o);
    if (lane == 0) g_hbias[dir][n] = bh[n] + acc;
}

// ================= fused GEMM (mma.sync fp16, M=128 x N=64, 3 CTAs/SM, 3-stage/1-sync) =================
// Z = [uhi; ulo] @ [Wz; Wz] (K-concat).
// Stage 12288B, SW128-swizzled 128B physical rows (16B-aligned, conflict-free):
//   A: 64 phys rows x 128B — phys row p holds logical rows p (chunks 0-3) and p+64 (chunks 4-7),
//      chunk index XORed with (p&7).
//   B: at +8192, 32 phys rows x 128B — phys row p holds logical rows p and p+32, same swizzle.
// 3-stage ring, prefetch distance 2, ONE __syncthreads per step.
// SMEM: [0,36864) stages | [36864,71680) zbuf fp32 128x68. bbuf (34816) aliases stages.
#define STAGE_B 12288
#define ZBUF_OFF 36864
#define SM_TOTAL 71680

__global__ __launch_bounds__(256, 3)
void qrn_gemm(int ld_f, int ld_b, int layer0, int store_ab,
              const float* __restrict__ bz_f_, const float* __restrict__ bz_b_,
              const float* __restrict__ bh_f_, const float* __restrict__ bh_b_)
{
    extern __shared__ __align__(16) char smem[];
    float* bbuf = (float*)smem;                      // aliases stages post-mainloop
    float* zbuf = (float*)(smem + ZBUF_OFF);         // 128 x 68 fp32
    __shared__ float s_bz[64], s_bh[64];
    __shared__ float s_pA[4][64], s_pB[4][64];

    const int tid = threadIdx.x, lane = tid & 31, warp = tid >> 5;
    const int wm = warp & 3, wn = warp >> 2;         // 4M x 2N warps; warp tile 32x32
    const int ch = blockIdx.y;
    const int dir = blockIdx.z;
    const int ld = dir ? ld_b : ld_f;
    const int row0 = ch*CHUNK, n0g = blockIdx.x*64;
    const uint32_t base = smem_u32(smem);

    if (tid < 64) {
        s_bz[tid] = (dir ? bz_b_ : bz_f_)[n0g + tid];
        s_bh[tid] = layer0 ? g_hbias[dir][n0g + tid]
                           : (dir ? bh_b_ : bh_f_)[n0g + tid];
    }

    const __half* wz = &g_wzT[ld][0];
    const __half* wh = &g_whT[ld][0];
    const int S = layer0 ? 24 : 32;     // phases of 8: uhi@Wz, ulo@Wz, x@WhTop, q@WhBot

    // ---- thread-constant copy geometry (SW128 swizzled dst, all 16B aligned) ----
    const int rA = tid >> 2, qq = tid & 3;           // rA: 0..63, qq: chunk 0..3
    const uint32_t dstA0 = (uint32_t)(rA*128 + ((qq       ^ (rA & 7))*16)); // logical row rA
    const uint32_t dstA1 = (uint32_t)(rA*128 + (((4 + qq) ^ (rA & 7))*16)); // logical row rA+64
    const uint32_t dstB  = 8192 + (uint32_t)((rA & 31)*128
                         + ((((rA >> 5)*4 + qq) ^ (rA & 7))*16));           // B logical row rA

    // ---- hoisted LDSM lane offsets (swizzled, per mi/pi x kk) ----
    uint32_t aoff[2][2], boff[2][2];
    #pragma unroll
    for (int mi = 0; mi < 2; mi++) {
        int r = wm*32 + mi*16 + (lane & 15);
        int p = r & 63, half = r >> 6;
        #pragma unroll
        for (int kk = 0; kk < 2; kk++) {
            int c = kk*2 + (lane >> 4);
            aoff[mi][kk] = (uint32_t)(p*128 + (((half*4 + c) ^ (p & 7))*16));
        }
    }
    #pragma unroll
    for (int pi = 0; pi < 2; pi++) {
        int n = wn*32 + pi*16 + ((lane >> 4) << 3) + (lane & 7);
        int p = n & 31, half = n >> 5;
        #pragma unroll
        for (int kk = 0; kk < 2; kk++) {
            int c = kk*2 + ((lane >> 3) & 1);
            boff[pi][kk] = 8192 + (uint32_t)(p*128 + (((half*4 + c) ^ (p & 7))*16));
        }
    }

    // ---- running source pointers (point at next stage to ISSUE) ----
    const __half *pA0, *pB;
    auto set_ptrs = [&](int s) {
        int ph = s >> 3, k = (s & 7)*32;
        const __half* Ab = (ph == 0) ? g_uhi : (ph == 1) ? g_ulo
                          : (ph == 2) ? g_xhi : g_qhi;
        pA0 = Ab + (size_t)(row0 + rA)*256 + k + qq*8;
        if (ph < 2) pB = wz + (size_t)(n0g + rA)*256 + k + qq*8;
        else        pB = wh + (size_t)(n0g + rA)*512 + ((ph == 3) ? 256 : 0) + k + qq*8;
    };

    float acc[2][4][4];
    #pragma unroll
    for (int mi = 0; mi < 2; mi++)
        #pragma unroll
        for (int ni = 0; ni < 4; ni++)
            #pragma unroll
            for (int j = 0; j < 4; j++) acc[mi][ni][j] = 0.f;

    // prologue: issue stages 0,1; pointers at stage 2
    set_ptrs(0);
    cpa16(base + dstA0, pA0); cpa16(base + dstA1, pA0 + 16384); cpa16(base + dstB, pB);
    CP_COMMIT();
    set_ptrs(1);
    cpa16(base + STAGE_B + dstA0, pA0); cpa16(base + STAGE_B + dstA1, pA0 + 16384);
    cpa16(base + STAGE_B + dstB, pB);
    CP_COMMIT();
    set_ptrs(2);

    for (int s = 0; s < S; s++) {
        CP_WAIT1();        // groups 0..s complete (exactly one committed per iter)
        __syncthreads();   // stage s visible; all warps done mma(s-1) -> buf (s-1)%3 free
        if (s + 2 < S) {
            uint32_t sb = base + (uint32_t)(((s + 2) % 3)*STAGE_B);
            cpa16(sb + dstA0, pA0); cpa16(sb + dstA1, pA0 + 16384); cpa16(sb + dstB, pB);
            if (((s + 3) & 7) == 0) set_ptrs(s + 3);
            else { pA0 += 32; pB += 32; }
        }
        CP_COMMIT();       // empty group when nothing issued keeps accounting uniform

        {   // ---- mma step on stage s ----
            const uint32_t stg = base + (uint32_t)((s % 3)*STAGE_B);
            #pragma unroll
            for (int kk = 0; kk < 2; kk++) {
                uint32_t aH[2][4], bb[4][2], t[4];
                ldsm_x4(aH[0], stg + aoff[0][kk]);
                ldsm_x4(aH[1], stg + aoff[1][kk]);
                ldsm_x4(t, stg + boff[0][kk]);
                bb[0][0]=t[0]; bb[0][1]=t[1]; bb[1][0]=t[2]; bb[1][1]=t[3];
                ldsm_x4(t, stg + boff[1][kk]);
                bb[2][0]=t[0]; bb[2][1]=t[1]; bb[3][0]=t[2]; bb[3][1]=t[3];
                #pragma unroll
                for (int mi = 0; mi < 2; mi++)
                    #pragma unroll
                    for (int ni = 0; ni < 4; ni++)
                        mma16816(acc[mi][ni], aH[mi], bb[ni]);
            }
        }

        if (s == 15) {     // z epilogue -> zbuf, reset acc for H phase
            #pragma unroll
            for (int mi = 0; mi < 2; mi++) {
                int r0 = wm*32 + mi*16 + (lane >> 2);
                #pragma unroll
                for (int ni = 0; ni < 4; ni++) {
                    int cl = wn*32 + ni*8 + (lane & 3)*2;
                    zbuf[r0*68 + cl]     = sigf(acc[mi][ni][0] + s_bz[cl]);
                    zbuf[r0*68 + cl + 1] = sigf(acc[mi][ni][1] + s_bz[cl+1]);
                    zbuf[(r0+8)*68 + cl]     = sigf(acc[mi][ni][2] + s_bz[cl]);
                    zbuf[(r0+8)*68 + cl + 1] = sigf(acc[mi][ni][3] + s_bz[cl+1]);
                    #pragma unroll
                    for (int j = 0; j < 4; j++) acc[mi][ni][j] = 0.f;
                }
            }
        }
    }
    __syncthreads();   // all MMA done; stage smem reusable as bbuf

    // ---- final epilogue: a = 1-z (into zbuf), b = z*tanh(h+bh) -> bbuf ----
    #pragma unroll
    for (int mi = 0; mi < 2; mi++) {
        int r0 = wm*32 + mi*16 + (lane >> 2);
        #pragma unroll
        for (int ni = 0; ni < 4; ni++) {
            int cl = wn*32 + ni*8 + (lane & 3)*2;
            #pragma unroll
            for (int hrow = 0; hrow < 2; hrow++) {
                int r = r0 + hrow*8;
                float z0 = zbuf[r*68 + cl], z1 = zbuf[r*68 + cl + 1];
                float h0 = tanhf_(acc[mi][ni][hrow*2+0] + s_bh[cl]);
                float h1 = tanhf_(acc[mi][ni][hrow*2+1] + s_bh[cl+1]);
                bbuf[r*68 + cl]     = z0*h0;
                bbuf[r*68 + cl + 1] = z1*h1;
                zbuf[r*68 + cl]     = 1.0f - z0;
                zbuf[r*68 + cl + 1] = 1.0f - z1;
            }
        }
    }
    __syncthreads();

    // ---- global a,b stores (128 rows x 64 cols) ----
    if (store_ab) {
        float* outA = dir ? g_ab2 : g_af;
        float* outB = dir ? g_bb2 : g_bf;
        #pragma unroll
        for (int i = 0; i < 8; i++) {
            int v = tid + i*256;          // 0..2047
            int r = v >> 4, c4 = (v & 15)*4;
            float4 va = *(float4*)(zbuf + r*68 + c4);
            float4 vb = *(float4*)(bbuf + r*68 + c4);
            size_t o = (size_t)(row0 + r)*256 + n0g + c4;
            *(float4*)(outA + o) = va;
            *(float4*)(outB + o) = vb;
        }
    }

    // ---- per-chunk scan composites (4 segs x 32 rows) ----
    {
        int cc = tid & 63, seg = tid >> 6;
        float pa = 1.0f, pb = 0.0f;
        if (dir == 0) {
            #pragma unroll 4
            for (int r = seg*32; r < seg*32 + 32; r++) {
                float a = zbuf[r*68 + cc], b = bbuf[r*68 + cc];
                pb = fmaf(a, pb, b); pa *= a;
            }
        } else {
            #pragma unroll 4
            for (int r = seg*32 + 31; r >= seg*32; r--) {
                float a = zbuf[r*68 + cc], b = bbuf[r*68 + cc];
                pb = fmaf(a, pb, b); pa *= a;
            }
        }
        s_pA[seg][cc] = pa; s_pB[seg][cc] = pb;
    }
    __syncthreads();
    if (tid < 64) {
        float A = 1.0f, B = 0.0f;
        if (dir == 0) {
            #pragma unroll
            for (int s = 0; s < 4; s++) { B = fmaf(s_pA[s][tid], B, s_pB[s][tid]); A *= s_pA[s][tid]; }
        } else {
            #pragma unroll
            for (int s = 3; s >= 0; s--) { B = fmaf(s_pA[s][tid], B, s_pB[s][tid]); A *= s_pA[s][tid]; }
        }
        size_t o = ((size_t)dir*NCH + ch)*256 + n0g + tid;
        g_cA[o] = A; g_cB[o] = B;
    }
}

// ================= scan kernels =================
__global__ __launch_bounds__(256) void scan_prefix()
{
    int dir = blockIdx.x, d = threadIdx.x;
    float cB = 0.f;
    if (dir == 0) {
        for (int c0 = 0; c0 < NCH; c0 += 8) {
            float a[8], b[8];
            #pragma unroll
            for (int i = 0; i < 8; i++) {
                a[i] = g_cA[(c0+i)*D_ + d];
                b[i] = g_cB[(c0+i)*D_ + d];
            }
            #pragma unroll
            for (int i = 0; i < 8; i++) {
                g_pref[(c0+i)*D_ + d] = cB;
                cB = fmaf(a[i], cB, b[i]);
            }
        }
    } else {
        for (int c0 = NCH - 8; c0 >= 0; c0 -= 8) {
            float a[8], b[8];
            #pragma unroll
            for (int i = 0; i < 8; i++) {
                a[i] = g_cA[(NCH + c0+i)*D_ + d];
                b[i] = g_cB[(NCH + c0+i)*D_ + d];
            }
            #pragma unroll
            for (int i = 7; i >= 0; i--) {
                g_pref[(NCH + c0+i)*D_ + d] = cB;
                cB = fmaf(a[i], cB, b[i]);
            }
        }
    }
}

// fused fwd+bwd apply + next-layer operand prep (h_fwd staged in smem)
__global__ __launch_bounds__(256) void scan_apply(const float* __restrict__ story)
{
    extern __shared__ float hbuf[];   // 128 x 256
    int d = threadIdx.x, ch = blockIdx.x;

    float h = g_pref[ch*D_ + d];
    size_t base = (size_t)ch*CHUNK*D_ + d;
    for (int j0 = 0; j0 < CHUNK; j0 += 8) {
        float a[8], b[8];
        #pragma unroll
        for (int i = 0; i < 8; i++) {
            size_t o = base + (size_t)(j0+i)*D_;
            a[i] = g_af[o]; b[i] = g_bf[o];
        }
        #pragma unroll
        for (int i = 0; i < 8; i++) {
            h = fmaf(a[i], h, b[i]);
            hbuf[(j0+i)*256 + d] = h;
        }
    }
    __syncthreads();

    float h2 = g_pref[(NCH + ch)*D_ + d];
    size_t base2 = ((size_t)ch*CHUNK + CHUNK-1)*D_ + d;
    for (int j0 = 0; j0 < CHUNK; j0 += 8) {
        float a[8], b[8], x[8];
        #pragma unroll
        for (int i = 0; i < 8; i++) {
            size_t o = base2 - (size_t)(j0+i)*D_;
            a[i] = g_ab2[o]; b[i] = g_bb2[o]; x[i] = story[o];
        }
        #pragma unroll
        for (int i = 0; i < 8; i++) {
            size_t o = base2 - (size_t)(j0+i)*D_;
            h2 = fmaf(a[i], h2, b[i]);
            float q = hbuf[(CHUNK-1-(j0+i))*256 + d] + h2;
            float u = x[i] * q;
            __half uh, ul;
            split2h(u, uh, ul);
            g_qhi[o] = __float2half_rn(q);
            g_uhi[o] = uh; g_ulo[o] = ul;
        }
    }
}

__global__ __launch_bounds__(256) void scan_final(float* __restrict__ out)
{
    int d = threadIdx.x;
    float cB = 0.f;
    for (int c0 = 0; c0 < NCH; c0 += 8) {
        float a[8], b[8];
        #pragma unroll
        for (int i = 0; i < 8; i++) {
            a[i] = g_cA[(c0+i)*D_ + d];
            b[i] = g_cB[(c0+i)*D_ + d];
        }
        #pragma unroll
        for (int i = 0; i < 8; i++)
            cB = fmaf(a[i], cB, b[i]);
    }
    out[d] = cB;
}

// ================= host launcher =================
extern "C" void kernel_launch(void* const* d_in, const int* in_sizes, int n_in,
                              void* d_out, int out_size)
{
    const float* story    = (const float*)d_in[0];
    const float* question = (const float*)d_in[1];
    const float* Wz_f     = (const float*)d_in[2];
    const float* bz_f     = (const float*)d_in[3];
    const float* Wh_f     = (const float*)d_in[4];
    const float* bh_f     = (const float*)d_in[5];
    const float* Wz_b     = (const float*)d_in[6];
    const float* bz_b     = (const float*)d_in[7];
    const float* Wh_b     = (const float*)d_in[8];
    const float* bh_b     = (const float*)d_in[9];
    float* out = (float*)d_out;

    cudaFuncSetAttribute(qrn_gemm,   cudaFuncAttributeMaxDynamicSharedMemorySize, SM_TOTAL);
    cudaFuncSetAttribute(scan_apply, cudaFuncAttributeMaxDynamicSharedMemorySize, 131072);

    // launch order: 3 predecessors then gemm at my-index 3 (ncu fixed window lands there)
    dim3 wb(32, 8), wg(8, 16, 10);
    prep_w<<<wg, wb>>>(Wz_f,           Wh_f,
                       Wz_b,           Wh_b,
                       Wz_f + 65536,   Wh_f + 131072,
                       Wz_b + 65536,   Wh_b + 131072,
                       Wz_f + 2*65536, Wh_f + 2*131072);
    prep_xu<<<T_*D_/512, 256>>>(story, question);
    qwh0<<<128, 128>>>(Wh_f, bh_f, Wh_b, bh_b, question);

    dim3 gg2(4, NCH, 2);   // (N-quarter, chunk, dir)
    dim3 gg1(4, NCH, 1);

    // ---- layer 0 (fwd+bwd merged) ----  <- my launch index 3: ncu capture target
    qrn_gemm<<<gg2, 256, SM_TOTAL>>>(0, 1, 1, 1, bz_f, bz_b, nullptr, nullptr);
    scan_prefix<<<2, 256>>>();
    scan_apply<<<NCH, 256, 131072>>>(story);

    // ---- layer 1 ----
    qrn_gemm<<<gg2, 256, SM_TOTAL>>>(2, 3, 0, 1, bz_f + 256, bz_b + 256, bh_f + 256, bh_b + 256);
    scan_prefix<<<2, 256>>>();
    scan_apply<<<NCH, 256, 131072>>>(story);

    // ---- layer 2 (forward only; composites only) ----
    qrn_gemm<<<gg1, 256, SM_TOTAL>>>(4, 4, 0, 0, bz_f + 512, bz_b + 512, bh_f + 512, bh_b + 512);
    scan_final<<<1, 256>>>(out);
}